// round 4
// baseline (speedup 1.0000x reference)
#include <cuda_runtime.h>
#include <cuda_bf16.h>

// RNN_72541997629806: 5-layer stacked LSTM (H=4), SEQ=610, BATCH=128,
// per-t Linear(4->1) + final FC [5,610] -> out [128,5].
//
// R4: single-warp systolic pipeline (1 batch elem / warp, 128 blocks x 32).
//   lane = layer*4 + j. 7 shuffles/step (4 shfl_up handoff + 3 xor gather,
//   xor results reused by next step AND the layer-4 tail). Gate dots in
//   packed fma.rn.f32x2 (weights in 16 x 64-bit regs, never addressable).
//   Sigmoid 0.5-prescale folded into i/f/o weights. No smem, no barriers.

#define H 4
#define NUM_LAYERS 5
#define SEQ 610
#define BATCH 128
#define NSTEP (SEQ + NUM_LAYERS - 1)   // 614 (even)

typedef unsigned long long ull;

__device__ __forceinline__ float tanh_fast(float x) {
    float y;
    asm("tanh.approx.f32 %0, %1;" : "=f"(y) : "f"(x));
    return y;
}
__device__ __forceinline__ ull pk2(float lo, float hi) {
    ull r;
    asm("mov.b64 %0, {%1, %2};" : "=l"(r) : "f"(lo), "f"(hi));
    return r;
}
__device__ __forceinline__ ull fma2(ull a, ull b, ull c) {
    ull d;
    asm("fma.rn.f32x2 %0, %1, %2, %3;" : "=l"(d) : "l"(a), "l"(b), "l"(c));
    return d;
}
__device__ __forceinline__ float hadd2(ull v) {
    float lo, hi;
    asm("mov.b64 {%0, %1}, %2;" : "=f"(lo), "=f"(hi) : "l"(v));
    return lo + hi;
}

__global__ __launch_bounds__(32, 1)
void lstm_warp_kernel(const float* __restrict__ x,      // [128,610,2]
                      const float* __restrict__ w_ih0,  // [16,2]
                      const float* __restrict__ w_ih,   // [4,16,4]
                      const float* __restrict__ w_hh,   // [5,16,4]
                      const float* __restrict__ b_ih,   // [5,16]
                      const float* __restrict__ b_hh,   // [5,16]
                      const float* __restrict__ w_lin,  // [1,4]
                      const float* __restrict__ b_lin,  // [1]
                      const float* __restrict__ w_fc,   // [5,610]
                      const float* __restrict__ b_fc,   // [5]
                      float* __restrict__ out)          // [128,5]
{
    const int lane     = threadIdx.x;
    const int layerRaw = lane >> 2;                  // 0..7
    const int layer    = layerRaw > 4 ? 4 : layerRaw;
    const int j        = lane & 3;
    const int b        = blockIdx.x;
    const bool isL0    = (layerRaw == 0);
    const bool isL4    = (layerRaw == 4);

    // ---- per-lane packed weights: gate rows {j,4+j,8+j,12+j} ----
    // wh columns j-relative: whX[q] multiplies (h[j^0],h[j^1]) / (h[j^2],h[j^3]).
    // wi: layer 0 absolute (input = x, padded); layers>=1 j-relative (input = p,
    // which arrives in j-relative order via shfl_up of the gathered quad).
    // i/f/o gates (q != 2) pre-scaled by 0.5 for sigmoid-via-tanh.
    ull wiA[4], wiB[4], whA[4], whB[4], bs2[4];
    #pragma unroll
    for (int q = 0; q < 4; ++q) {
        const int r = q * 4 + j;
        const float sc = (q == 2) ? 1.0f : 0.5f;
        float wv[4], hv[4];
        #pragma unroll
        for (int d = 0; d < 4; ++d) {
            if (layer == 0)
                wv[d] = (d < 2) ? sc * w_ih0[r * 2 + d] : 0.0f;           // absolute
            else
                wv[d] = sc * w_ih[(((layer - 1) * 16) + r) * 4 + (j ^ d)]; // j-rel
            hv[d] = sc * w_hh[((layer * 16) + r) * 4 + (j ^ d)];           // j-rel
        }
        wiA[q] = pk2(wv[0], wv[1]);  wiB[q] = pk2(wv[2], wv[3]);
        whA[q] = pk2(hv[0], hv[1]);  whB[q] = pk2(hv[2], hv[3]);
        bs2[q] = pk2(sc * (b_ih[layer * 16 + r] + b_hh[layer * 16 + r]), 0.0f);
    }

    // layer-4 extras (w_lin j-relative)
    float wl0 = w_lin[j ^ 0], wl1 = w_lin[j ^ 1], wl2 = w_lin[j ^ 2], wl3 = w_lin[j ^ 3];
    const float blin = b_lin[0];
    float accA = 0.0f, accB = 0.0f;
    if (isL4) {
        accA = b_fc[j];
        if (j == 0) accB = b_fc[4];
    }

    // ---- state: hpub = own h[j]; h1..h3 = h[j^1..3] (carried xor-gather) ----
    float hpub = 0.f, h1 = 0.f, h2 = 0.f, h3 = 0.f, cj = 0.f;

    const float* xb = x + (size_t)b * SEQ * 2;
    const float* wfcj = w_fc + j * SEQ;
    const float* wfc4 = w_fc + 4 * SEQ;

    #pragma unroll 1
    for (int s = 0; s < NSTEP; s += 2) {
        // uniform broadcast load of x[t=s] and x[t=s+1]
        const int sc2 = (s < SEQ - 1) ? s : (SEQ - 2);
        const float4 xq = *reinterpret_cast<const float4*>(xb + sc2 * 2);

        #pragma unroll
        for (int u = 0; u < 2; ++u) {
            const int ss = s + u;
            const int t  = ss - layerRaw;
            const bool active = (lane < 20) && ((unsigned)t < (unsigned)SEQ);

            // ---- layer handoff: prev layer's quad, j-relative order ----
            const float p0 = __shfl_up_sync(0xffffffffu, hpub, 4);
            const float p1 = __shfl_up_sync(0xffffffffu, h1, 4);
            const float p2 = __shfl_up_sync(0xffffffffu, h2, 4);
            const float p3 = __shfl_up_sync(0xffffffffu, h3, 4);

            ull iA, iB;
            if (isL0) {
                iA = u ? pk2(xq.z, xq.w) : pk2(xq.x, xq.y);
                iB = 0ull;   // (0.0f, 0.0f)
            } else {
                iA = pk2(p0, p1);
                iB = pk2(p2, p3);
            }
            const ull hA = pk2(hpub, h1);
            const ull hB = pk2(h2, h3);

            // ---- 4 gates: packed dot, then horizontal add ----
            const float gi = hadd2(fma2(whB[0], hB, fma2(whA[0], hA,
                               fma2(wiB[0], iB, fma2(wiA[0], iA, bs2[0])))));
            const float gf = hadd2(fma2(whB[1], hB, fma2(whA[1], hA,
                               fma2(wiB[1], iB, fma2(wiA[1], iA, bs2[1])))));
            const float gg = hadd2(fma2(whB[2], hB, fma2(whA[2], hA,
                               fma2(wiB[2], iB, fma2(wiA[2], iA, bs2[2])))));
            const float go = hadd2(fma2(whB[3], hB, fma2(whA[3], hA,
                               fma2(wiB[3], iB, fma2(wiA[3], iA, bs2[3])))));

            const float ig = fmaf(0.5f, tanh_fast(gi), 0.5f);
            const float fg = fmaf(0.5f, tanh_fast(gf), 0.5f);
            const float gt = tanh_fast(gg);
            const float og = fmaf(0.5f, tanh_fast(go), 0.5f);

            const float cn = fmaf(fg, cj, ig * gt);
            const float hn = og * tanh_fast(cn);

            cj   = active ? cn : cj;
            hpub = active ? hn : hpub;

            // ---- xor gather of updated h (feeds next step AND the tail) ----
            h1 = __shfl_xor_sync(0xffffffffu, hpub, 1);
            h2 = __shfl_xor_sync(0xffffffffu, hpub, 2);
            h3 = __shfl_xor_sync(0xffffffffu, hpub, 3);

            // ---- layer-4 tail: Linear(4->1) + FC accumulate ----
            if (isL4 && (unsigned)t < (unsigned)SEQ) {
                const float st = fmaf(wl3, h3, fmaf(wl2, h2,
                                 fmaf(wl1, h1, fmaf(wl0, hpub, blin))));
                accA = fmaf(__ldg(&wfcj[t]), st, accA);
                if (j == 0) accB = fmaf(__ldg(&wfc4[t]), st, accB);
            }
        }
    }

    if (isL4) {
        out[b * 5 + j] = accA;
        if (j == 0) out[b * 5 + 4] = accB;
    }
}

extern "C" void kernel_launch(void* const* d_in, const int* in_sizes, int n_in,
                              void* d_out, int out_size) {
    const float* x     = (const float*)d_in[0];
    const float* w_ih0 = (const float*)d_in[1];
    const float* w_ih  = (const float*)d_in[2];
    const float* w_hh  = (const float*)d_in[3];
    const float* b_ih  = (const float*)d_in[4];
    const float* b_hh  = (const float*)d_in[5];
    const float* w_lin = (const float*)d_in[6];
    const float* b_lin = (const float*)d_in[7];
    const float* w_fc  = (const float*)d_in[8];
    const float* b_fc  = (const float*)d_in[9];
    float* out = (float*)d_out;

    lstm_warp_kernel<<<BATCH, 32>>>(
        x, w_ih0, w_ih, w_hh, b_ih, b_hh, w_lin, b_lin, w_fc, b_fc, out);
}

// round 5
// speedup vs baseline: 1.5465x; 1.5465x over previous
#include <cuda_runtime.h>
#include <cuda_bf16.h>

// RNN_72541997629806: 5-layer stacked LSTM (H=4), SEQ=610, BATCH=128,
// per-t Linear(4->1) + final FC [5,610] -> out [128,5].
//
// R5: one warp = one batch element, fully uniform branch-free pipeline.
//   lane = stage*4 + j:
//     stages 0..4  : LSTM layers (gate slice j)
//     stage  5     : Linear(4->1)+FC accumulate (g0 preactivation IS the scalar)
//     stage  7 (28-31): x injection (publish x[t] components as hpub)
//   7 parallel shuffles of hpub per step; no branches, no smem, no barriers.
//   Sigmoid 0.5-prescale folded into i/f/o weights.

#define SEQ 610
#define BATCH 128
#define NSTEP (SEQ + 5)   // 615: stage-5 consumes t5 = ss-5 up to SEQ-1

__device__ __forceinline__ float tanh_fast(float x) {
    float y;
    asm("tanh.approx.f32 %0, %1;" : "=f"(y) : "f"(x));
    return y;
}

__global__ __launch_bounds__(32, 1)
void lstm_warp_kernel(const float* __restrict__ x,      // [128,610,2]
                      const float* __restrict__ w_ih0,  // [16,2]
                      const float* __restrict__ w_ih,   // [4,16,4]
                      const float* __restrict__ w_hh,   // [5,16,4]
                      const float* __restrict__ b_ih,   // [5,16]
                      const float* __restrict__ b_hh,   // [5,16]
                      const float* __restrict__ w_lin,  // [1,4]
                      const float* __restrict__ b_lin,  // [1]
                      const float* __restrict__ w_fc,   // [5,610]
                      const float* __restrict__ b_fc,   // [5]
                      float* __restrict__ out)          // [128,5]
{
    const int lane  = threadIdx.x;
    const int stage = lane >> 2;             // 0..7
    const int j     = lane & 3;
    const int b     = blockIdx.x;
    const int pbase = (lane - 4) & 28;       // base lane of previous stage quad

    // ---- named scalar weights (never addressable) ----
    float wi00=0,wi01=0,wi02=0,wi03=0, wi10=0,wi11=0,wi12=0,wi13=0;
    float wi20=0,wi21=0,wi22=0,wi23=0, wi30=0,wi31=0,wi32=0,wi33=0;
    float wh00=0,wh01=0,wh02=0,wh03=0, wh10=0,wh11=0,wh12=0,wh13=0;
    float wh20=0,wh21=0,wh22=0,wh23=0, wh30=0,wh31=0,wh32=0,wh33=0;
    float b0=0, b1=0, b2=0, b3=0;

    if (stage <= 4) {
        // LSTM lane: gate rows {j, 4+j, 8+j, 12+j} of layer `stage`.
        // wi columns absolute (handoff p is absolute order),
        // wh columns j-relative (xor gather), i/f/o pre-scaled 0.5.
        #define LQ(q, WI0,WI1,WI2,WI3, WH0,WH1,WH2,WH3, BQ) do {                  \
            const int   r  = (q) * 4 + j;                                         \
            const float sc = ((q) == 2) ? 1.0f : 0.5f;                            \
            if (stage == 0) {                                                     \
                WI0 = sc * w_ih0[r * 2 + 0];  WI1 = sc * w_ih0[r * 2 + 1];        \
                WI2 = 0.0f;                   WI3 = 0.0f;                          \
            } else {                                                              \
                const float* wp = w_ih + (((stage - 1) * 16) + r) * 4;            \
                WI0 = sc * wp[0]; WI1 = sc * wp[1];                               \
                WI2 = sc * wp[2]; WI3 = sc * wp[3];                               \
            }                                                                     \
            const float* hp = w_hh + ((stage * 16) + r) * 4;                      \
            WH0 = sc * hp[j ^ 0]; WH1 = sc * hp[j ^ 1];                           \
            WH2 = sc * hp[j ^ 2]; WH3 = sc * hp[j ^ 3];                           \
            BQ  = sc * (b_ih[stage * 16 + r] + b_hh[stage * 16 + r]);             \
        } while (0)
        LQ(0, wi00,wi01,wi02,wi03, wh00,wh01,wh02,wh03, b0);
        LQ(1, wi10,wi11,wi12,wi13, wh10,wh11,wh12,wh13, b1);
        LQ(2, wi20,wi21,wi22,wi23, wh20,wh21,wh22,wh23, b2);
        LQ(3, wi30,wi31,wi32,wi33, wh30,wh31,wh32,wh33, b3);
        #undef LQ
    } else if (stage == 5) {
        // Linear stage: g0 (pre-activation) = b_lin + dot(w_lin, h4)
        wi00 = w_lin[0]; wi01 = w_lin[1]; wi02 = w_lin[2]; wi03 = w_lin[3];
        b0 = b_lin[0];
    }
    // stages 6,7 keep all-zero weights (their gates are inert)

    float accA = (stage == 5) ? b_fc[j] : 0.0f;
    float accB = (lane == 20) ? b_fc[4] : 0.0f;
    const float* wfcj = w_fc + j * SEQ;
    const float* wfc4 = w_fc + 4 * SEQ;

    // ---- state ----
    const float* xb = x + (size_t)b * SEQ * 2;
    float2 x0 = *reinterpret_cast<const float2*>(xb);
    float hpub = (lane == 28) ? x0.x : ((lane == 29) ? x0.y : 0.0f);
    float cj = 0.0f;

    #pragma unroll 1
    for (int ss = 0; ss < NSTEP; ++ss) {
        // x for the NEXT step's injection (uniform broadcast load)
        int txn = ss + 1; txn = (txn < SEQ) ? txn : (SEQ - 1);
        const float2 xv = *reinterpret_cast<const float2*>(xb + txn * 2);

        // ---- 7 parallel shuffles of last step's published h ----
        const float h0 = hpub;
        const float h1 = __shfl_xor_sync(0xffffffffu, hpub, 1);
        const float h2 = __shfl_xor_sync(0xffffffffu, hpub, 2);
        const float h3 = __shfl_xor_sync(0xffffffffu, hpub, 3);
        const float p0 = __shfl_sync(0xffffffffu, hpub, pbase);
        const float p1 = __shfl_sync(0xffffffffu, hpub, pbase + 1);
        const float p2 = __shfl_sync(0xffffffffu, hpub, pbase + 2);
        const float p3 = __shfl_sync(0xffffffffu, hpub, pbase + 3);

        // ---- gates: own-h/bias chain starts early, shuffle terms join late ----
        const float g0 = fmaf(wh03,h3, fmaf(wh02,h2, fmaf(wh01,h1, fmaf(wh00,h0, b0))))
                       + fmaf(wi03,p3, fmaf(wi02,p2, fmaf(wi01,p1, wi00 * p0)));
        const float g1 = fmaf(wh13,h3, fmaf(wh12,h2, fmaf(wh11,h1, fmaf(wh10,h0, b1))))
                       + fmaf(wi13,p3, fmaf(wi12,p2, fmaf(wi11,p1, wi10 * p0)));
        const float g2 = fmaf(wh23,h3, fmaf(wh22,h2, fmaf(wh21,h1, fmaf(wh20,h0, b2))))
                       + fmaf(wi23,p3, fmaf(wi22,p2, fmaf(wi21,p1, wi20 * p0)));
        const float g3 = fmaf(wh33,h3, fmaf(wh32,h2, fmaf(wh31,h1, fmaf(wh30,h0, b3))))
                       + fmaf(wi33,p3, fmaf(wi32,p2, fmaf(wi31,p1, wi30 * p0)));

        const float ig = fmaf(0.5f, tanh_fast(g0), 0.5f);
        const float fg = fmaf(0.5f, tanh_fast(g1), 0.5f);
        const float gt = tanh_fast(g2);
        const float og = fmaf(0.5f, tanh_fast(g3), 0.5f);
        const float cn = fmaf(fg, cj, ig * gt);
        const float hn = og * tanh_fast(cn);

        // ---- state update with validity selects (no branches) ----
        const bool tv = (unsigned)(ss - stage) < (unsigned)SEQ;
        cj = tv ? cn : cj;
        float hc = tv ? hn : hpub;
        float xc = (lane & 1) ? xv.y : xv.x;
        xc = (lane & 2) ? 0.0f : xc;
        hpub = (lane >= 28) ? xc : hc;

        // ---- FC accumulate (uniform; stage-5 g0 is the Linear scalar) ----
        const int  t5 = ss - 5;
        const bool v5 = (unsigned)t5 < (unsigned)SEQ;
        const int  tc = v5 ? t5 : 0;
        const float sv = v5 ? g0 : 0.0f;
        accA = fmaf(__ldg(wfcj + tc), sv, accA);
        accB = fmaf(__ldg(wfc4 + tc), sv, accB);
    }

    if (stage == 5) out[b * 5 + j] = accA;
    if (lane == 20) out[b * 5 + 4] = accB;
}

extern "C" void kernel_launch(void* const* d_in, const int* in_sizes, int n_in,
                              void* d_out, int out_size) {
    const float* x     = (const float*)d_in[0];
    const float* w_ih0 = (const float*)d_in[1];
    const float* w_ih  = (const float*)d_in[2];
    const float* w_hh  = (const float*)d_in[3];
    const float* b_ih  = (const float*)d_in[4];
    const float* b_hh  = (const float*)d_in[5];
    const float* w_lin = (const float*)d_in[6];
    const float* b_lin = (const float*)d_in[7];
    const float* w_fc  = (const float*)d_in[8];
    const float* b_fc  = (const float*)d_in[9];
    float* out = (float*)d_out;

    lstm_warp_kernel<<<BATCH, 32>>>(
        x, w_ih0, w_ih, w_hh, b_ih, b_hh, w_lin, b_lin, w_fc, b_fc, out);
}

// round 6
// speedup vs baseline: 2.4148x; 1.5615x over previous
#include <cuda_runtime.h>
#include <cuda_bf16.h>

// RNN_72541997629806: 5-layer stacked LSTM (H=4), SEQ=610, BATCH=128,
// per-t Linear(4->1) + final FC [5,610] -> out [128,5].
//
// R6: one warp = one batch element, branch-free systolic pipeline.
//   lane = stage*4 + j: stages 0-4 LSTM layers, stage 5 Linear+FC,
//   lanes 28-31 x-injection. 7 parallel shuffles of hpub per step.
//   NEW vs R5: x + w_fc staged in SMEM (no LDG in loop); guarded 5-step
//   prologue then select-free steady loop (validity proven structurally:
//   zero-padded x and zero-padded w_fc rows; out-of-range stage outputs
//   are never consumed by in-range stages).

#define SEQ 610
#define BATCH 128
#define NSTEP (SEQ + 5)      // ss = 0 .. 614

__device__ __forceinline__ float tanh_fast(float x) {
    float y;
    asm("tanh.approx.f32 %0, %1;" : "=f"(y) : "f"(x));
    return y;
}

__global__ __launch_bounds__(32, 1)
void lstm_warp_kernel(const float* __restrict__ x,      // [128,610,2]
                      const float* __restrict__ w_ih0,  // [16,2]
                      const float* __restrict__ w_ih,   // [4,16,4]
                      const float* __restrict__ w_hh,   // [5,16,4]
                      const float* __restrict__ b_ih,   // [5,16]
                      const float* __restrict__ b_hh,   // [5,16]
                      const float* __restrict__ w_lin,  // [1,4]
                      const float* __restrict__ b_lin,  // [1]
                      const float* __restrict__ w_fc,   // [5,610]
                      const float* __restrict__ b_fc,   // [5]
                      float* __restrict__ out)          // [128,5]
{
    const int lane  = threadIdx.x;
    const int stage = lane >> 2;             // 0..7
    const int j     = lane & 3;
    const int b     = blockIdx.x;
    const int pbase = (lane - 4) & 28;       // base lane of previous stage quad
    const bool isX  = (lane >= 28);

    // ---- named scalar weights (never addressable) ----
    float wi00=0,wi01=0,wi02=0,wi03=0, wi10=0,wi11=0,wi12=0,wi13=0;
    float wi20=0,wi21=0,wi22=0,wi23=0, wi30=0,wi31=0,wi32=0,wi33=0;
    float wh00=0,wh01=0,wh02=0,wh03=0, wh10=0,wh11=0,wh12=0,wh13=0;
    float wh20=0,wh21=0,wh22=0,wh23=0, wh30=0,wh31=0,wh32=0,wh33=0;
    float b0=0, b1=0, b2=0, b3=0;

    if (stage <= 4) {
        #define LQ(q, WI0,WI1,WI2,WI3, WH0,WH1,WH2,WH3, BQ) do {                  \
            const int   r  = (q) * 4 + j;                                         \
            const float sc = ((q) == 2) ? 1.0f : 0.5f;                            \
            if (stage == 0) {                                                     \
                WI0 = sc * w_ih0[r * 2 + 0];  WI1 = sc * w_ih0[r * 2 + 1];        \
                WI2 = 0.0f;                   WI3 = 0.0f;                          \
            } else {                                                              \
                const float* wp = w_ih + (((stage - 1) * 16) + r) * 4;            \
                WI0 = sc * wp[0]; WI1 = sc * wp[1];                               \
                WI2 = sc * wp[2]; WI3 = sc * wp[3];                               \
            }                                                                     \
            const float* hp = w_hh + ((stage * 16) + r) * 4;                      \
            WH0 = sc * hp[j ^ 0]; WH1 = sc * hp[j ^ 1];                           \
            WH2 = sc * hp[j ^ 2]; WH3 = sc * hp[j ^ 3];                           \
            BQ  = sc * (b_ih[stage * 16 + r] + b_hh[stage * 16 + r]);             \
        } while (0)
        LQ(0, wi00,wi01,wi02,wi03, wh00,wh01,wh02,wh03, b0);
        LQ(1, wi10,wi11,wi12,wi13, wh10,wh11,wh12,wh13, b1);
        LQ(2, wi20,wi21,wi22,wi23, wh20,wh21,wh22,wh23, b2);
        LQ(3, wi30,wi31,wi32,wi33, wh30,wh31,wh32,wh33, b3);
        #undef LQ
    } else if (stage == 5) {
        wi00 = w_lin[0]; wi01 = w_lin[1]; wi02 = w_lin[2]; wi03 = w_lin[3];
        b0 = b_lin[0];
    }

    // ---- SMEM staging: x row (zero-padded) + w_fc rows (5-entry zero head) ----
    __shared__ float2 xs2[SEQ + 8];              // [0..609]=x, rest 0
    __shared__ float  wfc_s[5][SEQ + 16];        // row idx ss: [5..614]=w_fc[t=ss-5]
    {
        const float2* xb2 = reinterpret_cast<const float2*>(x + (size_t)b * SEQ * 2);
        for (int i = lane; i < SEQ + 8; i += 32)
            xs2[i] = (i < SEQ) ? xb2[i] : make_float2(0.0f, 0.0f);
        #pragma unroll
        for (int r = 0; r < 5; ++r)
            for (int i = lane; i < SEQ + 16; i += 32)
                wfc_s[r][i] = (i >= 5 && i < SEQ + 5) ? w_fc[r * SEQ + (i - 5)] : 0.0f;
    }
    __syncwarp();

    const float* wA = wfc_s[(stage == 5) ? j : 0];   // per-lane FC row
    const float* w4 = wfc_s[4];

    float accA = (stage == 5) ? b_fc[j] : 0.0f;
    float accB = (lane == 20) ? b_fc[4] : 0.0f;

    // ---- state ----
    float hpub = (lane == 28) ? xs2[0].x : ((lane == 29) ? xs2[0].y : 0.0f);
    float cj = 0.0f;

    // One pipeline step. GUARD=true applies validity selects (prologue only).
    #define STEP(ss, GUARD) do {                                                   \
        const float2 xv = xs2[(ss) + 1];                                           \
        const float h0 = hpub;                                                     \
        const float h1 = __shfl_xor_sync(0xffffffffu, hpub, 1);                    \
        const float h2 = __shfl_xor_sync(0xffffffffu, hpub, 2);                    \
        const float h3 = __shfl_xor_sync(0xffffffffu, hpub, 3);                    \
        const float p0 = __shfl_sync(0xffffffffu, hpub, pbase);                    \
        const float p1 = __shfl_sync(0xffffffffu, hpub, pbase + 1);                \
        const float p2 = __shfl_sync(0xffffffffu, hpub, pbase + 2);                \
        const float p3 = __shfl_sync(0xffffffffu, hpub, pbase + 3);                \
        const float g0 = fmaf(wh03,h3, fmaf(wh02,h2, fmaf(wh01,h1, fmaf(wh00,h0, b0)))) \
                       + fmaf(wi03,p3, fmaf(wi02,p2, fmaf(wi01,p1, wi00 * p0)));   \
        const float g1 = fmaf(wh13,h3, fmaf(wh12,h2, fmaf(wh11,h1, fmaf(wh10,h0, b1)))) \
                       + fmaf(wi13,p3, fmaf(wi12,p2, fmaf(wi11,p1, wi10 * p0)));   \
        const float g2 = fmaf(wh23,h3, fmaf(wh22,h2, fmaf(wh21,h1, fmaf(wh20,h0, b2)))) \
                       + fmaf(wi23,p3, fmaf(wi22,p2, fmaf(wi21,p1, wi20 * p0)));   \
        const float g3 = fmaf(wh33,h3, fmaf(wh32,h2, fmaf(wh31,h1, fmaf(wh30,h0, b3)))) \
                       + fmaf(wi33,p3, fmaf(wi32,p2, fmaf(wi31,p1, wi30 * p0)));   \
        const float gt = tanh_fast(g2);                                            \
        const float ig = fmaf(0.5f, tanh_fast(g0), 0.5f);                          \
        const float fg = fmaf(0.5f, tanh_fast(g1), 0.5f);                          \
        const float og = fmaf(0.5f, tanh_fast(g3), 0.5f);                          \
        const float cn = fmaf(fg, cj, ig * gt);                                    \
        const float hn = og * tanh_fast(cn);                                       \
        float xc = (lane & 1) ? xv.y : xv.x;                                       \
        xc = (lane & 2) ? 0.0f : xc;                                               \
        if (GUARD) {                                                               \
            const bool tv = (unsigned)((ss) - stage) < (unsigned)SEQ;              \
            cj = tv ? cn : cj;                                                     \
            const float hc = tv ? hn : hpub;                                       \
            hpub = isX ? xc : hc;                                                  \
        } else {                                                                   \
            cj = cn;                                                               \
            hpub = isX ? xc : hn;                                                  \
        }                                                                          \
        accA = fmaf(wA[(ss)], g0, accA);                                           \
        accB = fmaf(w4[(ss)], g0, accB);                                           \
    } while (0)

    // prologue: validity selects active
    #pragma unroll 1
    for (int ss = 0; ss < 5; ++ss) STEP(ss, true);
    // steady + epilogue: select-free (structural validity, see header comment)
    #pragma unroll 1
    for (int ss = 5; ss < NSTEP; ++ss) STEP(ss, false);

    #undef STEP

    if (stage == 5) out[b * 5 + j] = accA;
    if (lane == 20) out[b * 5 + 4] = accB;
}

extern "C" void kernel_launch(void* const* d_in, const int* in_sizes, int n_in,
                              void* d_out, int out_size) {
    const float* x     = (const float*)d_in[0];
    const float* w_ih0 = (const float*)d_in[1];
    const float* w_ih  = (const float*)d_in[2];
    const float* w_hh  = (const float*)d_in[3];
    const float* b_ih  = (const float*)d_in[4];
    const float* b_hh  = (const float*)d_in[5];
    const float* w_lin = (const float*)d_in[6];
    const float* b_lin = (const float*)d_in[7];
    const float* w_fc  = (const float*)d_in[8];
    const float* b_fc  = (const float*)d_in[9];
    float* out = (float*)d_out;

    lstm_warp_kernel<<<BATCH, 32>>>(
        x, w_ih0, w_ih, w_hh, b_ih, b_hh, w_lin, b_lin, w_fc, b_fc, out);
}